// round 9
// baseline (speedup 1.0000x reference)
#include <cuda_runtime.h>
#include <cuda_bf16.h>
#include <math.h>
#include <stdint.h>

// ---------------------------------------------------------------------------
// VelocityHead: B=64, T=4096, D=256, DE=16, NB=8, alpha=0.3, thresh=0.1
// Outputs (flat fp32): vel [B,T,256], move_flag [B,T], mov_logits [B,T,2]
// Tensor path: mma.sync bf16 (3-MMA hi/lo split), portable PTX (no tcgen05).
// 128 tokens/CTA, 512 threads, double-buffered W panels.
// ---------------------------------------------------------------------------

#define B_    64
#define T_    4096
#define BT_   (B_*T_)
#define FLAG_OFF  (BT_*256)
#define LOG_OFF   (FLAG_OFF + BT_)
#define PI_F 3.14159265358979323846f

typedef unsigned long long ull;

// scratch (allocation-free: device globals)
__device__ float g_feats[BT_*6];
__device__ int   g_bins[BT_];
// weights bf16 hi/lo, [K][N] row-major (k rows of 256)
__device__ __nv_bfloat16 g_w2h[256*256];
__device__ __nv_bfloat16 g_w2l[256*256];
__device__ __nv_bfloat16 g_owh[256*256];
__device__ __nv_bfloat16 g_owl[256*256];
__device__ float g_embtab[8*256];     // emb[bin] @ OW[256:272,:]

// ------------------------- packed f32x2 helpers ----------------------------
__device__ __forceinline__ ull pk2(float lo, float hi){
    ull r; asm("mov.b64 %0, {%1,%2};" : "=l"(r) : "f"(lo), "f"(hi)); return r;
}
__device__ __forceinline__ void upk2(ull v, float &lo, float &hi){
    asm("mov.b64 {%0,%1}, %2;" : "=f"(lo), "=f"(hi) : "l"(v));
}
__device__ __forceinline__ void fma2(ull &d, ull a, ull b){
    asm("fma.rn.f32x2 %0, %1, %2, %0;" : "+l"(d) : "l"(a), "l"(b));
}

// ------------------------- mma/ldmatrix helpers ----------------------------
__device__ __forceinline__ uint32_t smem_u32(const void* p){
    uint32_t a;
    asm("{ .reg .u64 t; cvta.to.shared.u64 t, %1; cvt.u32.u64 %0, t; }" : "=r"(a) : "l"(p));
    return a;
}
__device__ __forceinline__ void ldm4(uint32_t* r, uint32_t addr){
    asm volatile("ldmatrix.sync.aligned.m8n8.x4.shared.b16 {%0,%1,%2,%3}, [%4];"
        : "=r"(r[0]), "=r"(r[1]), "=r"(r[2]), "=r"(r[3]) : "r"(addr));
}
__device__ __forceinline__ void ldm4t(uint32_t* r, uint32_t addr){
    asm volatile("ldmatrix.sync.aligned.m8n8.x4.trans.shared.b16 {%0,%1,%2,%3}, [%4];"
        : "=r"(r[0]), "=r"(r[1]), "=r"(r[2]), "=r"(r[3]) : "r"(addr));
}
__device__ __forceinline__ void mma_bf16(float* c, const uint32_t* a, uint32_t b0, uint32_t b1){
    asm volatile("mma.sync.aligned.m16n8k16.row.col.f32.bf16.bf16.f32 "
        "{%0,%1,%2,%3}, {%4,%5,%6,%7}, {%8,%9}, {%0,%1,%2,%3};"
        : "+f"(c[0]), "+f"(c[1]), "+f"(c[2]), "+f"(c[3])
        : "r"(a[0]), "r"(a[1]), "r"(a[2]), "r"(a[3]), "r"(b0), "r"(b1));
}

// ---------------------------- bf16 split -----------------------------------
__device__ __forceinline__ void hsplit(float x, unsigned short &h, unsigned short &lo){
    __nv_bfloat16 hb = __float2bfloat16(x);
    float r = x - __bfloat162float(hb);
    h  = __bfloat16_as_ushort(hb);
    lo = __bfloat16_as_ushort(__float2bfloat16(r));
}

// ===========================================================================
// prep: split weights to bf16 hi/lo [K][N]; fold emb through OW tail.
// ===========================================================================
__global__ void prep_kernel(const float* __restrict__ W2, const float* __restrict__ OW,
                            const float* __restrict__ EMB){
    int i = blockIdx.x*blockDim.x + threadIdx.x;
    int stride = gridDim.x*blockDim.x;
    for (int x = i; x < 256*256; x += stride){
        float w = W2[x];
        __nv_bfloat16 h = __float2bfloat16(w);
        g_w2h[x] = h;
        g_w2l[x] = __float2bfloat16(w - __bfloat162float(h));
        float w2 = OW[x];                // rows 0..255 of OW
        __nv_bfloat16 h2 = __float2bfloat16(w2);
        g_owh[x] = h2;
        g_owl[x] = __float2bfloat16(w2 - __bfloat162float(h2));
    }
    for (int x = i; x < 8*256; x += stride){
        int j = x >> 8, n = x & 255;
        float s = 0.f;
        #pragma unroll
        for (int e = 0; e < 16; ++e)
            s += EMB[j*16 + e] * OW[(256 + e)*256 + n];
        g_embtab[x] = s;
    }
}

// ===========================================================================
// Kernel 1: features + windowed EMA (exact to fp32: 0.7^64 ~ 1.2e-10)
// ===========================================================================
__global__ __launch_bounds__(256)
void feat_kernel(const float* __restrict__ pos, const float* __restrict__ ts,
                 float* __restrict__ flag_out)
{
    __shared__ float sx[320], sd[320];
    const int b    = blockIdx.y;
    const int t0   = blockIdx.x * 256;
    const int tid  = threadIdx.x;
    const float* P  = pos + (size_t)b * T_ * 2;
    const float* Ts = ts  + (size_t)b * T_;

    float dPx_m, dPy_m, dt_m;
    auto compx = [&](int t, float &sp, float &dn, float &dx, float &dy, float &dtv){
        float dxx, dyy, dt;
        if (t == 0) { dxx = 0.f; dyy = 0.f; dt = 1.f; }
        else {
            dxx = P[2*t]   - P[2*t-2];
            dyy = P[2*t+1] - P[2*t-1];
            float dtr = Ts[t] - Ts[t-1];
            dtr = (dtr > 0.01f) ? dtr : 1.0f;
            dt  = fminf(fmaxf(dtr, 0.1f), 1000.f);
        }
        float dist = sqrtf(dxx*dxx + dyy*dyy) + 1e-8f;
        float dts  = fminf(fmaxf(dt, 0.1f), 1000.f) * 0.1f;
        sp = fminf(fmaxf(dist / (dts + 1e-6f), 0.f), 10.f);
        float dir = atan2f(dyy + 1e-8f, dxx + 1e-8f);
        dn = fminf(fmaxf(dir * (1.0f/PI_F), -1.f), 1.f);
        dx = dxx; dy = dyy; dtv = dt;
    };

    { float sp, dn; compx(t0 + tid, sp, dn, dPx_m, dPy_m, dt_m); sx[64+tid]=sp; sd[64+tid]=dn; }
    if (tid < 64 && t0 > 0){ float sp,dn,a0,a1,a2; compx(t0-64+tid,sp,dn,a0,a1,a2); sx[tid]=sp; sd[tid]=dn; }
    __syncthreads();

    const int   t  = t0 + tid;
    const float cA = 0.3f, cC = 0.7f;
    float ys, yd;
    if (t == 0) { ys = sx[64]; yd = sd[64]; }
    else {
        const int Kw     = (t < 64) ? t : 64;
        const int lstart = (t - Kw + 1) - t0 + 64;
        float ss = 0.f, sdd = 0.f;
        for (int l = lstart; l <= tid + 64; ++l) { ss = cC*ss + sx[l]; sdd = cC*sdd + sd[l]; }
        ys = cA*ss; yd = cA*sdd;
        if (t < 64) {
            float p = 1.f;
            for (int i = 0; i < t; ++i) p *= cC;
            ys += p * sx[64]; yd += p * sd[64];
        }
    }

    const float flag = (ys > 0.1f) ? 1.f : 0.f;
    const size_t g = (size_t)b * T_ + t;
    float* f = g_feats + g*6;
    f[0] = dPx_m; f[1] = dPy_m; f[2] = dt_m; f[3] = ys; f[4] = yd; f[5] = flag;

    int bin = (int)((yd + 1.0f) * 4.0f);
    bin = min(max(bin, 0), 7);
    if (flag == 0.f) bin = 0;
    g_bins[g]   = bin;
    flag_out[g] = flag;
}

// ===========================================================================
// Kernel 2: fused MLP with mma.sync bf16 split.
// 128 tokens/CTA, 512 thr (16 warps, 4m x 4n). Warp tile 32x64.
// A resident in smem (bf16 hi/lo, 528B rows). W double-buffered k32 chunks.
// ===========================================================================
#define NT 512
#define ASTRIDE 528
#define AH_OFF 0
#define AL_OFF 67584
#define WB_OFF 135168
#define WHALF  16896              // one half (hi or lo) of one W buffer
#define WBUFSZ (2*WHALF)          // 33792: hi+lo of one buffer
#define CONST_OFF 202752
#define SMEM_SZ (CONST_OFF + 8192)   // consts 6144B + lnp 1024B + lgp 1024B

__device__ __forceinline__ void gemm_tc(unsigned char* smemc, uint32_t sb,
                                        const unsigned char* gWh, const unsigned char* gWl,
                                        float acc[2][8][4], int tid)
{
    const int lane = tid & 31, warp = tid >> 5;
    const int nw = warp & 3, mw = warp >> 2;
    const int arow   = mw*32 + (lane & 15);
    const int acoladd= (lane >= 16) ? 8 : 0;
    const int brow   = (lane & 15);
    const int bcol   = nw*64 + ((lane >= 16) ? 8 : 0);

    // prefetch chunk 0 to regs
    uint4 rgh[2], rgl[2];
    #pragma unroll
    for (int j = 0; j < 2; ++j){
        int u = tid + j*NT, row = u >> 5, seg = u & 31;
        rgh[j] = *(const uint4*)(gWh + row*512 + seg*16);
        rgl[j] = *(const uint4*)(gWl + row*512 + seg*16);
    }

    #pragma unroll 1
    for (int c = 0; c < 8; ++c){
        __syncthreads();   // all warps done mma(c-1); buf[c&1] last read at mma(c-2)
        {
            unsigned char* dst = smemc + WB_OFF + (c & 1)*WBUFSZ;
            #pragma unroll
            for (int j = 0; j < 2; ++j){
                int u = tid + j*NT, row = u >> 5, seg = u & 31;
                *(uint4*)(dst + row*ASTRIDE + seg*16) = rgh[j];
                *(uint4*)(dst + WHALF + row*ASTRIDE + seg*16) = rgl[j];
            }
        }
        if (c < 7){
            #pragma unroll
            for (int j = 0; j < 2; ++j){
                int u = tid + j*NT, row = u >> 5, seg = u & 31;
                rgh[j] = *(const uint4*)(gWh + (size_t)(c+1)*16384 + row*512 + seg*16);
                rgl[j] = *(const uint4*)(gWl + (size_t)(c+1)*16384 + row*512 + seg*16);
            }
        }
        __syncthreads();
        const uint32_t whb = sb + WB_OFF + (c & 1)*WBUFSZ;
        const uint32_t wlb = whb + WHALF;
        #pragma unroll
        for (int kk = 0; kk < 32; kk += 16){
            uint32_t ah[2][4], al[2][4];
            const uint32_t acol = (uint32_t)(c*32 + kk + acoladd)*2;
            ldm4(ah[0], sb + AH_OFF + arow*ASTRIDE + acol);
            ldm4(ah[1], sb + AH_OFF + (arow+16)*ASTRIDE + acol);
            ldm4(al[0], sb + AL_OFF + arow*ASTRIDE + acol);
            ldm4(al[1], sb + AL_OFF + (arow+16)*ASTRIDE + acol);
            #pragma unroll
            for (int nt = 0; nt < 4; ++nt){
                uint32_t bh[4], bl[4];
                const uint32_t boff = (uint32_t)(kk + brow)*ASTRIDE + (uint32_t)(bcol + nt*16)*2;
                ldm4t(bh, whb + boff);
                ldm4t(bl, wlb + boff);
                // term-major: same accumulator revisited only every 4 mma
                mma_bf16(acc[0][2*nt],   ah[0], bh[0], bh[1]);
                mma_bf16(acc[1][2*nt],   ah[1], bh[0], bh[1]);
                mma_bf16(acc[0][2*nt+1], ah[0], bh[2], bh[3]);
                mma_bf16(acc[1][2*nt+1], ah[1], bh[2], bh[3]);
                mma_bf16(acc[0][2*nt],   ah[0], bl[0], bl[1]);
                mma_bf16(acc[1][2*nt],   ah[1], bl[0], bl[1]);
                mma_bf16(acc[0][2*nt+1], ah[0], bl[2], bl[3]);
                mma_bf16(acc[1][2*nt+1], ah[1], bl[2], bl[3]);
                mma_bf16(acc[0][2*nt],   al[0], bh[0], bh[1]);
                mma_bf16(acc[1][2*nt],   al[1], bh[0], bh[1]);
                mma_bf16(acc[0][2*nt+1], al[0], bh[2], bh[3]);
                mma_bf16(acc[1][2*nt+1], al[1], bh[2], bh[3]);
            }
        }
    }
}

__global__ __launch_bounds__(NT, 1)
void mlp3_kernel(const float* __restrict__ W1,  const float* __restrict__ EB1,
                 const float* __restrict__ G1,  const float* __restrict__ LB1,
                 const float* __restrict__ EB2, const float* __restrict__ G2,
                 const float* __restrict__ LB2, const float* __restrict__ OB,
                 const float* __restrict__ MW,  const float* __restrict__ MB,
                 float* __restrict__ out)
{
    extern __shared__ unsigned char smemc[];
    const uint32_t sb = smem_u32(smemc);
    const int tid = threadIdx.x;
    const int warp = tid >> 5, lane = tid & 31;
    const int t0 = blockIdx.x * 128;

    float*  eb2S = (float*)(smemc + CONST_OFF);
    float*  g2S  = eb2S + 256;
    float*  lb2S = eb2S + 512;
    float*  obS  = eb2S + 768;
    float*  mwS  = eb2S + 1024;          // 512 floats
    float2* lnp  = (float2*)(eb2S + 1536);   // 128 float2
    float2* lgp  = lnp + 128;                // 128 float2 (ends at 8192B)

    float*  featS = (float*)(smemc + WB_OFF);        // 128x8 fp32
    float*  w1S   = featS + 1024;                     // 6x256 fp32

    // stage consts + feats + W1
    if (tid < 256){ eb2S[tid] = EB2[tid]; g2S[tid] = G2[tid]; lb2S[tid] = LB2[tid]; obS[tid] = OB[tid]; }
    mwS[tid] = MW[tid];
    for (int i = tid; i < 128*6; i += NT) featS[(i/6)*8 + (i%6)] = g_feats[(size_t)t0*6 + i];
    for (int i = tid; i < 1536;  i += NT) w1S[i] = W1[i];
    if (tid < 128){ lnp[tid] = make_float2(0.f,0.f); lgp[tid] = make_float2(0.f,0.f); }
    __syncthreads();

    // ============ GEMM1 (K=6, fp32 FFMA2) + LN1 + ReLU -> A hi/lo ==========
    {
        const int r0 = warp*8, c0 = lane*4;
        ull acc1[8][4];
        {
            float4 b0 = *(const float4*)(EB1 + c0);
            float4 b1 = *(const float4*)(EB1 + 128 + c0);
            ull p0 = pk2(b0.x,b0.y), p1 = pk2(b0.z,b0.w);
            ull p2 = pk2(b1.x,b1.y), p3 = pk2(b1.z,b1.w);
            #pragma unroll
            for (int i = 0; i < 8; ++i){ acc1[i][0]=p0; acc1[i][1]=p1; acc1[i][2]=p2; acc1[i][3]=p3; }
        }
        #pragma unroll
        for (int k = 0; k < 6; ++k){
            float4 w0 = *(const float4*)(w1S + k*256 + c0);
            float4 w1v= *(const float4*)(w1S + k*256 + 128 + c0);
            ull wp0 = pk2(w0.x,w0.y), wp1 = pk2(w0.z,w0.w);
            ull wp2 = pk2(w1v.x,w1v.y), wp3 = pk2(w1v.z,w1v.w);
            #pragma unroll
            for (int i = 0; i < 8; ++i){
                float f = featS[(r0+i)*8 + k];
                ull fp = pk2(f, f);
                fma2(acc1[i][0], fp, wp0); fma2(acc1[i][1], fp, wp1);
                fma2(acc1[i][2], fp, wp2); fma2(acc1[i][3], fp, wp3);
            }
        }
        float4 gA = *(const float4*)(G1 + c0);
        float4 gB = *(const float4*)(G1 + 128 + c0);
        float4 bA = *(const float4*)(LB1 + c0);
        float4 bB = *(const float4*)(LB1 + 128 + c0);
        float gg[8] = {gA.x,gA.y,gA.z,gA.w,gB.x,gB.y,gB.z,gB.w};
        float bb[8] = {bA.x,bA.y,bA.z,bA.w,bB.x,bB.y,bB.z,bB.w};
        #pragma unroll
        for (int i = 0; i < 8; ++i){
            float v[8];
            upk2(acc1[i][0], v[0], v[1]); upk2(acc1[i][1], v[2], v[3]);
            upk2(acc1[i][2], v[4], v[5]); upk2(acc1[i][3], v[6], v[7]);
            float s = 0.f, q = 0.f;
            #pragma unroll
            for (int j = 0; j < 8; ++j){ s += v[j]; q += v[j]*v[j]; }
            #pragma unroll
            for (int off = 16; off; off >>= 1){
                s += __shfl_xor_sync(0xffffffffu, s, off);
                q += __shfl_xor_sync(0xffffffffu, q, off);
            }
            float mean = s * (1.f/256.f);
            float var  = fmaf(-mean, mean, q * (1.f/256.f));
            float rstd = rsqrtf(var + 1e-5f);
            const int row = r0 + i;
            #pragma unroll
            for (int gph = 0; gph < 2; ++gph){
                const int cc = gph*128 + c0;
                unsigned short h0,h1,h2,h3, l0v,l1v,l2v,l3v;
                float o0 = fmaxf((v[gph*4+0]-mean)*rstd*gg[gph*4+0] + bb[gph*4+0], 0.f);
                float o1 = fmaxf((v[gph*4+1]-mean)*rstd*gg[gph*4+1] + bb[gph*4+1], 0.f);
                float o2 = fmaxf((v[gph*4+2]-mean)*rstd*gg[gph*4+2] + bb[gph*4+2], 0.f);
                float o3 = fmaxf((v[gph*4+3]-mean)*rstd*gg[gph*4+3] + bb[gph*4+3], 0.f);
                hsplit(o0,h0,l0v); hsplit(o1,h1,l1v); hsplit(o2,h2,l2v); hsplit(o3,h3,l3v);
                *(uint2*)(smemc + AH_OFF + row*ASTRIDE + cc*2) =
                    make_uint2((uint32_t)h0 | ((uint32_t)h1<<16), (uint32_t)h2 | ((uint32_t)h3<<16));
                *(uint2*)(smemc + AL_OFF + row*ASTRIDE + cc*2) =
                    make_uint2((uint32_t)l0v | ((uint32_t)l1v<<16), (uint32_t)l2v | ((uint32_t)l3v<<16));
            }
        }
    }
    // NOTE: featS/w1S live in the W buffer area; gemm_tc's first sync orders
    // the A-panel stores and the last reads of featS/w1S before overwrite.

    const int nw = warp & 3, mw = warp >> 2;
    const int mbase = mw*32, nbase = nw*64;

    float acc[2][8][4];
    #pragma unroll
    for (int a1 = 0; a1 < 2; ++a1)
        #pragma unroll
        for (int a2 = 0; a2 < 8; ++a2)
            #pragma unroll
            for (int a3 = 0; a3 < 4; ++a3) acc[a1][a2][a3] = 0.f;

    // ================= GEMM2: h @ W2 =======================================
    gemm_tc(smemc, sb, (const unsigned char*)g_w2h, (const unsigned char*)g_w2l, acc, tid);
    __syncthreads();   // all mma done reading A before LN2 overwrites it

    // ================= LN2 (bias + stats + normalize -> A hi/lo) ===========
    #pragma unroll
    for (int mt = 0; mt < 2; ++mt)
    #pragma unroll
    for (int h = 0; h < 2; ++h){
        const int r = mbase + mt*16 + h*8 + (lane>>2);
        float s = 0.f, q = 0.f;
        #pragma unroll
        for (int nt = 0; nt < 8; ++nt){
            const int cA = nbase + nt*8 + 2*(lane&3);
            float x0 = acc[mt][nt][2*h]   + eb2S[cA];
            float x1 = acc[mt][nt][2*h+1] + eb2S[cA+1];
            s += x0 + x1; q += x0*x0 + x1*x1;
        }
        s += __shfl_xor_sync(0xffffffffu, s, 1); q += __shfl_xor_sync(0xffffffffu, q, 1);
        s += __shfl_xor_sync(0xffffffffu, s, 2); q += __shfl_xor_sync(0xffffffffu, q, 2);
        if ((lane & 3) == 0){ atomicAdd(&lnp[r].x, s); atomicAdd(&lnp[r].y, q); }
    }
    __syncthreads();
    if (tid < 128){
        float2 p = lnp[tid];
        float mean = p.x * (1.f/256.f);
        float var  = fmaf(-mean, mean, p.y * (1.f/256.f));
        lnp[tid] = make_float2(mean, rsqrtf(var + 1e-5f));
    }
    __syncthreads();
    #pragma unroll
    for (int mt = 0; mt < 2; ++mt)
    #pragma unroll
    for (int h = 0; h < 2; ++h){
        const int r = mbase + mt*16 + h*8 + (lane>>2);
        const float2 st = lnp[r];
        #pragma unroll
        for (int nt = 0; nt < 8; ++nt){
            const int cA = nbase + nt*8 + 2*(lane&3);
            float x0 = (acc[mt][nt][2*h]   + eb2S[cA]   - st.x)*st.y*g2S[cA]   + lb2S[cA];
            float x1 = (acc[mt][nt][2*h+1] + eb2S[cA+1] - st.x)*st.y*g2S[cA+1] + lb2S[cA+1];
            unsigned short h0,h1,l0v,l1v;
            hsplit(x0,h0,l0v); hsplit(x1,h1,l1v);
            *(uint32_t*)(smemc + AH_OFF + r*ASTRIDE + cA*2) = (uint32_t)h0 | ((uint32_t)h1<<16);
            *(uint32_t*)(smemc + AL_OFF + r*ASTRIDE + cA*2) = (uint32_t)l0v | ((uint32_t)l1v<<16);
        }
    }

    #pragma unroll
    for (int a1 = 0; a1 < 2; ++a1)
        #pragma unroll
        for (int a2 = 0; a2 < 8; ++a2)
            #pragma unroll
            for (int a3 = 0; a3 < 4; ++a3) acc[a1][a2][a3] = 0.f;

    // ================= GEMM3: base @ OW[:256] ==============================
    // gemm_tc's leading __syncthreads() orders the LN2 A-panel stores.
    gemm_tc(smemc, sb, (const unsigned char*)g_owh, (const unsigned char*)g_owl, acc, tid);

    // ================= epilogue: vel + mov_logits ==========================
    #pragma unroll
    for (int mt = 0; mt < 2; ++mt)
    #pragma unroll
    for (int h = 0; h < 2; ++h){
        const int r = mbase + mt*16 + h*8 + (lane>>2);
        const int bin = g_bins[t0 + r];
        const float* et = g_embtab + bin*256;
        float s0 = 0.f, s1 = 0.f;
        #pragma unroll
        for (int nt = 0; nt < 8; ++nt){
            const int cA = nbase + nt*8 + 2*(lane&3);
            float v0 = acc[mt][nt][2*h]   + obS[cA]   + et[cA];
            float v1 = acc[mt][nt][2*h+1] + obS[cA+1] + et[cA+1];
            *(float2*)(out + (size_t)(t0 + r)*256 + cA) = make_float2(v0, v1);
            s0 += v0*mwS[2*cA]   + v1*mwS[2*cA+2];
            s1 += v0*mwS[2*cA+1] + v1*mwS[2*cA+3];
        }
        s0 += __shfl_xor_sync(0xffffffffu, s0, 1); s1 += __shfl_xor_sync(0xffffffffu, s1, 1);
        s0 += __shfl_xor_sync(0xffffffffu, s0, 2); s1 += __shfl_xor_sync(0xffffffffu, s1, 2);
        if ((lane & 3) == 0){ atomicAdd(&lgp[r].x, s0); atomicAdd(&lgp[r].y, s1); }
    }
    __syncthreads();
    if (tid < 128){
        float2 p = lgp[tid];
        out[LOG_OFF + (size_t)(t0 + tid)*2 + 0] = p.x + MB[0];
        out[LOG_OFF + (size_t)(t0 + tid)*2 + 1] = p.y + MB[1];
    }
}

// ===========================================================================
extern "C" void kernel_launch(void* const* d_in, const int* in_sizes, int n_in,
                              void* d_out, int out_size)
{
    (void)in_sizes; (void)n_in; (void)out_size;
    const float* pos = (const float*)d_in[0];
    const float* ts  = (const float*)d_in[1];
    const float* W1  = (const float*)d_in[2];
    const float* EB1 = (const float*)d_in[3];
    const float* G1  = (const float*)d_in[4];
    const float* LB1 = (const float*)d_in[5];
    const float* W2  = (const float*)d_in[6];
    const float* EB2 = (const float*)d_in[7];
    const float* G2  = (const float*)d_in[8];
    const float* LB2 = (const float*)d_in[9];
    const float* EMB = (const float*)d_in[10];
    const float* OW  = (const float*)d_in[11];
    const float* OB  = (const float*)d_in[12];
    const float* MW  = (const float*)d_in[13];
    const float* MB  = (const float*)d_in[14];
    float* out = (float*)d_out;

    cudaFuncSetAttribute(mlp3_kernel, cudaFuncAttributeMaxDynamicSharedMemorySize, SMEM_SZ);

    dim3 g1(T_/256, B_);
    feat_kernel<<<g1, 256>>>(pos, ts, out + FLAG_OFF);
    prep_kernel<<<128, 256>>>(W2, OW, EMB);
    mlp3_kernel<<<BT_/128, NT, SMEM_SZ>>>(W1, EB1, G1, LB1, EB2, G2, LB2,
                                          OB, MW, MB, out);
}

// round 12
// speedup vs baseline: 1.3184x; 1.3184x over previous
#include <cuda_runtime.h>
#include <cuda_fp16.h>
#include <math.h>
#include <stdint.h>

// ---------------------------------------------------------------------------
// VelocityHead: B=64, T=4096, D=256, DE=16, NB=8, alpha=0.3, thresh=0.1
// Outputs (flat fp32): vel [B,T,256], move_flag [B,T], mov_logits [B,T,2]
// Tensor path: mma.sync f16, 2-product split (A single f16, W = f16 hi+lo).
// 64 tokens/CTA, 256 thr, 2 CTAs/SM.
// ---------------------------------------------------------------------------

#define B_    64
#define T_    4096
#define BT_   (B_*T_)
#define FLAG_OFF  (BT_*256)
#define LOG_OFF   (FLAG_OFF + BT_)
#define PI_F 3.14159265358979323846f

typedef unsigned long long ull;

// scratch (allocation-free: device globals)
__device__ float g_feats[BT_*6];
__device__ int   g_bins[BT_];
// weights f16 hi/lo, [K][N] row-major (k rows of 256)
__device__ __half g_w2h[256*256];
__device__ __half g_w2l[256*256];
__device__ __half g_owh[256*256];
__device__ __half g_owl[256*256];
__device__ float g_embtab[8*256];     // emb[bin] @ OW[256:272,:]

// ------------------------- packed f32x2 helpers ----------------------------
__device__ __forceinline__ ull pk2(float lo, float hi){
    ull r; asm("mov.b64 %0, {%1,%2};" : "=l"(r) : "f"(lo), "f"(hi)); return r;
}
__device__ __forceinline__ void upk2(ull v, float &lo, float &hi){
    asm("mov.b64 {%0,%1}, %2;" : "=f"(lo), "=f"(hi) : "l"(v));
}
__device__ __forceinline__ void fma2(ull &d, ull a, ull b){
    asm("fma.rn.f32x2 %0, %1, %2, %0;" : "+l"(d) : "l"(a), "l"(b));
}

// ------------------------- mma/ldmatrix helpers ----------------------------
__device__ __forceinline__ uint32_t smem_u32(const void* p){
    uint32_t a;
    asm("{ .reg .u64 t; cvta.to.shared.u64 t, %1; cvt.u32.u64 %0, t; }" : "=r"(a) : "l"(p));
    return a;
}
__device__ __forceinline__ void ldm4(uint32_t* r, uint32_t addr){
    asm volatile("ldmatrix.sync.aligned.m8n8.x4.shared.b16 {%0,%1,%2,%3}, [%4];"
        : "=r"(r[0]), "=r"(r[1]), "=r"(r[2]), "=r"(r[3]) : "r"(addr));
}
__device__ __forceinline__ void ldm4t(uint32_t* r, uint32_t addr){
    asm volatile("ldmatrix.sync.aligned.m8n8.x4.trans.shared.b16 {%0,%1,%2,%3}, [%4];"
        : "=r"(r[0]), "=r"(r[1]), "=r"(r[2]), "=r"(r[3]) : "r"(addr));
}
__device__ __forceinline__ void mma_f16(float* c, const uint32_t* a, uint32_t b0, uint32_t b1){
    asm volatile("mma.sync.aligned.m16n8k16.row.col.f32.f16.f16.f32 "
        "{%0,%1,%2,%3}, {%4,%5,%6,%7}, {%8,%9}, {%0,%1,%2,%3};"
        : "+f"(c[0]), "+f"(c[1]), "+f"(c[2]), "+f"(c[3])
        : "r"(a[0]), "r"(a[1]), "r"(a[2]), "r"(a[3]), "r"(b0), "r"(b1));
}

__device__ __forceinline__ unsigned short f2h(float x){
    return __half_as_ushort(__float2half_rn(x));
}

// ===========================================================================
// prep: split weights to f16 hi/lo [K][N]; fold emb through OW tail.
// ===========================================================================
__global__ void prep_kernel(const float* __restrict__ W2, const float* __restrict__ OW,
                            const float* __restrict__ EMB){
    int i = blockIdx.x*blockDim.x + threadIdx.x;
    int stride = gridDim.x*blockDim.x;
    for (int x = i; x < 256*256; x += stride){
        float w = W2[x];
        __half h = __float2half_rn(w);
        g_w2h[x] = h;
        g_w2l[x] = __float2half_rn(w - __half2float(h));
        float w2 = OW[x];                // rows 0..255 of OW
        __half h2 = __float2half_rn(w2);
        g_owh[x] = h2;
        g_owl[x] = __float2half_rn(w2 - __half2float(h2));
    }
    for (int x = i; x < 8*256; x += stride){
        int j = x >> 8, n = x & 255;
        float s = 0.f;
        #pragma unroll
        for (int e = 0; e < 16; ++e)
            s += EMB[j*16 + e] * OW[(256 + e)*256 + n];
        g_embtab[x] = s;
    }
}

// ===========================================================================
// Kernel 1: features + windowed EMA (exact to fp32: 0.7^64 ~ 1.2e-10)
// ===========================================================================
__global__ __launch_bounds__(256)
void feat_kernel(const float* __restrict__ pos, const float* __restrict__ ts,
                 float* __restrict__ flag_out)
{
    __shared__ float sx[320], sd[320];
    const int b    = blockIdx.y;
    const int t0   = blockIdx.x * 256;
    const int tid  = threadIdx.x;
    const float* P  = pos + (size_t)b * T_ * 2;
    const float* Ts = ts  + (size_t)b * T_;

    float dPx_m, dPy_m, dt_m;
    auto compx = [&](int t, float &sp, float &dn, float &dx, float &dy, float &dtv){
        float dxx, dyy, dt;
        if (t == 0) { dxx = 0.f; dyy = 0.f; dt = 1.f; }
        else {
            dxx = P[2*t]   - P[2*t-2];
            dyy = P[2*t+1] - P[2*t-1];
            float dtr = Ts[t] - Ts[t-1];
            dtr = (dtr > 0.01f) ? dtr : 1.0f;
            dt  = fminf(fmaxf(dtr, 0.1f), 1000.f);
        }
        float dist = sqrtf(dxx*dxx + dyy*dyy) + 1e-8f;
        float dts  = fminf(fmaxf(dt, 0.1f), 1000.f) * 0.1f;
        sp = fminf(fmaxf(dist / (dts + 1e-6f), 0.f), 10.f);
        float dir = atan2f(dyy + 1e-8f, dxx + 1e-8f);
        dn = fminf(fmaxf(dir * (1.0f/PI_F), -1.f), 1.f);
        dx = dxx; dy = dyy; dtv = dt;
    };

    { float sp, dn; compx(t0 + tid, sp, dn, dPx_m, dPy_m, dt_m); sx[64+tid]=sp; sd[64+tid]=dn; }
    if (tid < 64 && t0 > 0){ float sp,dn,a0,a1,a2; compx(t0-64+tid,sp,dn,a0,a1,a2); sx[tid]=sp; sd[tid]=dn; }
    __syncthreads();

    const int   t  = t0 + tid;
    const float cA = 0.3f, cC = 0.7f;
    float ys, yd;
    if (t == 0) { ys = sx[64]; yd = sd[64]; }
    else {
        const int Kw     = (t < 64) ? t : 64;
        const int lstart = (t - Kw + 1) - t0 + 64;
        float ss = 0.f, sdd = 0.f;
        for (int l = lstart; l <= tid + 64; ++l) { ss = cC*ss + sx[l]; sdd = cC*sdd + sd[l]; }
        ys = cA*ss; yd = cA*sdd;
        if (t < 64) {
            float p = 1.f;
            for (int i = 0; i < t; ++i) p *= cC;
            ys += p * sx[64]; yd += p * sd[64];
        }
    }

    const float flag = (ys > 0.1f) ? 1.f : 0.f;
    const size_t g = (size_t)b * T_ + t;
    float* f = g_feats + g*6;
    f[0] = dPx_m; f[1] = dPy_m; f[2] = dt_m; f[3] = ys; f[4] = yd; f[5] = flag;

    int bin = (int)((yd + 1.0f) * 4.0f);
    bin = min(max(bin, 0), 7);
    if (flag == 0.f) bin = 0;
    g_bins[g]   = bin;
    flag_out[g] = flag;
}

// ===========================================================================
// Kernel 2: fused MLP with mma.sync f16 2-product split.
// 64 tokens/CTA, 256 thr (8 warps). Warp tile 32x64 (2 m16 x 8 n8).
// A resident in smem (single f16 panel, 528B rows). W k32 chunks (Wh+Wl).
// ===========================================================================
#define NT 256
#define ASTRIDE 528
#define AH_OFF 0                  // 64 x 528 = 33792
#define WB_OFF 33792              // Wh chunk; Wl at +WHALF
#define WHALF  16896              // 32 rows x 528
#define CONST_OFF 67584
#define SMEM_SZ (CONST_OFF + 7168)

__device__ __forceinline__ void gemm_tc(unsigned char* smemc, uint32_t sb,
                                        const unsigned char* gWh, const unsigned char* gWl,
                                        float acc[2][8][4], int tid)
{
    const int lane = tid & 31, warp = tid >> 5;
    const int nw = warp & 3, mw = warp >> 2;
    const int arow   = mw*32 + (lane & 15);
    const int acoladd= (lane >= 16) ? 8 : 0;
    const int brow   = (lane & 15);
    const int bcol   = nw*64 + ((lane >= 16) ? 8 : 0);

    #pragma unroll 1
    for (int c = 0; c < 8; ++c){
        __syncthreads();   // previous chunk fully consumed (or A-panel ready)
        #pragma unroll
        for (int j = 0; j < 4; ++j){
            int u = tid + j*256, row = u >> 5, seg = u & 31;
            uint4 h = *(const uint4*)(gWh + (size_t)c*16384 + row*512 + seg*16);
            uint4 l = *(const uint4*)(gWl + (size_t)c*16384 + row*512 + seg*16);
            *(uint4*)(smemc + WB_OFF + row*ASTRIDE + seg*16) = h;
            *(uint4*)(smemc + WB_OFF + WHALF + row*ASTRIDE + seg*16) = l;
        }
        __syncthreads();
        const uint32_t whb = sb + WB_OFF;
        const uint32_t wlb = whb + WHALF;
        #pragma unroll
        for (int kk = 0; kk < 32; kk += 16){
            uint32_t ah[2][4];
            const uint32_t acol = (uint32_t)(c*32 + kk + acoladd)*2;
            ldm4(ah[0], sb + AH_OFF + arow*ASTRIDE + acol);
            ldm4(ah[1], sb + AH_OFF + (arow+16)*ASTRIDE + acol);
            #pragma unroll
            for (int nt = 0; nt < 4; ++nt){
                uint32_t bh[4], bl[4];
                const uint32_t boff = (uint32_t)(kk + brow)*ASTRIDE + (uint32_t)(bcol + nt*16)*2;
                ldm4t(bh, whb + boff);
                ldm4t(bl, wlb + boff);
                // term-major: same accumulator revisited only every 4 mma
                mma_f16(acc[0][2*nt],   ah[0], bh[0], bh[1]);
                mma_f16(acc[1][2*nt],   ah[1], bh[0], bh[1]);
                mma_f16(acc[0][2*nt+1], ah[0], bh[2], bh[3]);
                mma_f16(acc[1][2*nt+1], ah[1], bh[2], bh[3]);
                mma_f16(acc[0][2*nt],   ah[0], bl[0], bl[1]);
                mma_f16(acc[1][2*nt],   ah[1], bl[0], bl[1]);
                mma_f16(acc[0][2*nt+1], ah[0], bl[2], bl[3]);
                mma_f16(acc[1][2*nt+1], ah[1], bl[2], bl[3]);
            }
        }
    }
}

__global__ __launch_bounds__(NT, 2)
void mlp3_kernel(const float* __restrict__ W1,  const float* __restrict__ EB1,
                 const float* __restrict__ G1,  const float* __restrict__ LB1,
                 const float* __restrict__ EB2, const float* __restrict__ G2,
                 const float* __restrict__ LB2, const float* __restrict__ OB,
                 const float* __restrict__ MW,  const float* __restrict__ MB,
                 float* __restrict__ out)
{
    extern __shared__ unsigned char smemc[];
    const uint32_t sb = smem_u32(smemc);
    const int tid = threadIdx.x;
    const int warp = tid >> 5, lane = tid & 31;
    const int t0 = blockIdx.x * 64;

    float*  eb2S = (float*)(smemc + CONST_OFF);
    float*  g2S  = eb2S + 256;
    float*  lb2S = eb2S + 512;
    float*  obS  = eb2S + 768;
    float*  mwS  = eb2S + 1024;          // 512 floats
    float2* lnp  = (float2*)(eb2S + 1536);   // 64 float2
    float2* lgp  = lnp + 64;                 // 64 float2

    float*  featS = (float*)(smemc + WB_OFF);        // 64x8 fp32
    float*  w1S   = featS + 512;                      // 6x256 fp32

    // stage consts + feats + W1
    eb2S[tid] = EB2[tid]; g2S[tid] = G2[tid]; lb2S[tid] = LB2[tid]; obS[tid] = OB[tid];
    mwS[tid] = MW[tid]; mwS[tid+256] = MW[tid+256];
    for (int i = tid; i < 64*6; i += NT) featS[(i/6)*8 + (i%6)] = g_feats[(size_t)t0*6 + i];
    for (int i = tid; i < 1536;  i += NT) w1S[i] = W1[i];
    if (tid < 64){ lnp[tid] = make_float2(0.f,0.f); lgp[tid] = make_float2(0.f,0.f); }
    __syncthreads();

    // ============ GEMM1 (K=6, fp32 FFMA2) + LN1 + ReLU -> A f16 panel ======
    {
        const int r0 = warp*8, c0 = lane*4;
        ull acc1[8][4];
        {
            float4 b0 = *(const float4*)(EB1 + c0);
            float4 b1 = *(const float4*)(EB1 + 128 + c0);
            ull p0 = pk2(b0.x,b0.y), p1 = pk2(b0.z,b0.w);
            ull p2 = pk2(b1.x,b1.y), p3 = pk2(b1.z,b1.w);
            #pragma unroll
            for (int i = 0; i < 8; ++i){ acc1[i][0]=p0; acc1[i][1]=p1; acc1[i][2]=p2; acc1[i][3]=p3; }
        }
        #pragma unroll
        for (int k = 0; k < 6; ++k){
            float4 w0 = *(const float4*)(w1S + k*256 + c0);
            float4 w1v= *(const float4*)(w1S + k*256 + 128 + c0);
            ull wp0 = pk2(w0.x,w0.y), wp1 = pk2(w0.z,w0.w);
            ull wp2 = pk2(w1v.x,w1v.y), wp3 = pk2(w1v.z,w1v.w);
            #pragma unroll
            for (int i = 0; i < 8; ++i){
                float f = featS[(r0+i)*8 + k];
                ull fp = pk2(f, f);
                fma2(acc1[i][0], fp, wp0); fma2(acc1[i][1], fp, wp1);
                fma2(acc1[i][2], fp, wp2); fma2(acc1[i][3], fp, wp3);
            }
        }
        float4 gA = *(const float4*)(G1 + c0);
        float4 gB = *(const float4*)(G1 + 128 + c0);
        float4 bA = *(const float4*)(LB1 + c0);
        float4 bB = *(const float4*)(LB1 + 128 + c0);
        float gg[8] = {gA.x,gA.y,gA.z,gA.w,gB.x,gB.y,gB.z,gB.w};
        float bb[8] = {bA.x,bA.y,bA.z,bA.w,bB.x,bB.y,bB.z,bB.w};
        #pragma unroll
        for (int i = 0; i < 8; ++i){
            float v[8];
            upk2(acc1[i][0], v[0], v[1]); upk2(acc1[i][1], v[2], v[3]);
            upk2(acc1[i][2], v[4], v[5]); upk2(acc1[i][3], v[6], v[7]);
            float s = 0.f, q = 0.f;
            #pragma unroll
            for (int j = 0; j < 8; ++j){ s += v[j]; q += v[j]*v[j]; }
            #pragma unroll
            for (int off = 16; off; off >>= 1){
                s += __shfl_xor_sync(0xffffffffu, s, off);
                q += __shfl_xor_sync(0xffffffffu, q, off);
            }
            float mean = s * (1.f/256.f);
            float var  = fmaf(-mean, mean, q * (1.f/256.f));
            float rstd = rsqrtf(var + 1e-5f);
            const int row = r0 + i;
            #pragma unroll
            for (int gph = 0; gph < 2; ++gph){
                const int cc = gph*128 + c0;
                float o0 = fmaxf((v[gph*4+0]-mean)*rstd*gg[gph*4+0] + bb[gph*4+0], 0.f);
                float o1 = fmaxf((v[gph*4+1]-mean)*rstd*gg[gph*4+1] + bb[gph*4+1], 0.f);
                float o2 = fmaxf((v[gph*4+2]-mean)*rstd*gg[gph*4+2] + bb[gph*4+2], 0.f);
                float o3 = fmaxf((v[gph*4+3]-mean)*rstd*gg[gph*4+3] + bb[gph*4+3], 0.f);
                *(uint2*)(smemc + AH_OFF + row*ASTRIDE + cc*2) =
                    make_uint2((uint32_t)f2h(o0) | ((uint32_t)f2h(o1)<<16),
                               (uint32_t)f2h(o2) | ((uint32_t)f2h(o3)<<16));
            }
        }
    }
    // NOTE: featS/w1S live in the W buffer area; gemm_tc's first sync orders
    // the A-panel stores and the last reads of featS/w1S before overwrite.

    const int nw = warp & 3, mw = warp >> 2;
    const int mbase = mw*32, nbase = nw*64;

    float acc[2][8][4];
    #pragma unroll
    for (int a1 = 0; a1 < 2; ++a1)
        #pragma unroll
        for (int a2 = 0; a2 < 8; ++a2)
            #pragma unroll
            for (int a3 = 0; a3 < 4; ++a3) acc[a1][a2][a3] = 0.f;

    // ================= GEMM2: h @ W2 =======================================
    gemm_tc(smemc, sb, (const unsigned char*)g_w2h, (const unsigned char*)g_w2l, acc, tid);
    __syncthreads();   // all mma done reading A before LN2 overwrites it

    // ================= LN2 (bias + stats + normalize -> A f16) =============
    #pragma unroll
    for (int mt = 0; mt < 2; ++mt)
    #pragma unroll
    for (int h = 0; h < 2; ++h){
        const int r = mbase + mt*16 + h*8 + (lane>>2);
        float s = 0.f, q = 0.f;
        #pragma unroll
        for (int nt = 0; nt < 8; ++nt){
            const int cA = nbase + nt*8 + 2*(lane&3);
            float x0 = acc[mt][nt][2*h]   + eb2S[cA];
            float x1 = acc[mt][nt][2*h+1] + eb2S[cA+1];
            s += x0 + x1; q += x0*x0 + x1*x1;
        }
        s += __shfl_xor_sync(0xffffffffu, s, 1); q += __shfl_xor_sync(0xffffffffu, q, 1);
        s += __shfl_xor_sync(0xffffffffu, s, 2); q += __shfl_xor_sync(0xffffffffu, q, 2);
        if ((lane & 3) == 0){ atomicAdd(&lnp[r].x, s); atomicAdd(&lnp[r].y, q); }
    }
    __syncthreads();
    if (tid < 64){
        float2 p = lnp[tid];
        float mean = p.x * (1.f/256.f);
        float var  = fmaf(-mean, mean, p.y * (1.f/256.f));
        lnp[tid] = make_float2(mean, rsqrtf(var + 1e-5f));
    }
    __syncthreads();
    #pragma unroll
    for (int mt = 0; mt < 2; ++mt)
    #pragma unroll
    for (int h = 0; h < 2; ++h){
        const int r = mbase + mt*16 + h*8 + (lane>>2);
        const float2 st = lnp[r];
        #pragma unroll
        for (int nt = 0; nt < 8; ++nt){
            const int cA = nbase + nt*8 + 2*(lane&3);
            float x0 = (acc[mt][nt][2*h]   + eb2S[cA]   - st.x)*st.y*g2S[cA]   + lb2S[cA];
            float x1 = (acc[mt][nt][2*h+1] + eb2S[cA+1] - st.x)*st.y*g2S[cA+1] + lb2S[cA+1];
            *(uint32_t*)(smemc + AH_OFF + r*ASTRIDE + cA*2) =
                (uint32_t)f2h(x0) | ((uint32_t)f2h(x1)<<16);
        }
    }

    #pragma unroll
    for (int a1 = 0; a1 < 2; ++a1)
        #pragma unroll
        for (int a2 = 0; a2 < 8; ++a2)
            #pragma unroll
            for (int a3 = 0; a3 < 4; ++a3) acc[a1][a2][a3] = 0.f;

    // ================= GEMM3: base @ OW[:256] ==============================
    // gemm_tc's leading __syncthreads() orders the LN2 A-panel stores.
    gemm_tc(smemc, sb, (const unsigned char*)g_owh, (const unsigned char*)g_owl, acc, tid);

    // ================= epilogue: vel + mov_logits ==========================
    #pragma unroll
    for (int mt = 0; mt < 2; ++mt)
    #pragma unroll
    for (int h = 0; h < 2; ++h){
        const int r = mbase + mt*16 + h*8 + (lane>>2);
        const int bin = g_bins[t0 + r];
        const float* et = g_embtab + bin*256;
        float s0 = 0.f, s1 = 0.f;
        #pragma unroll
        for (int nt = 0; nt < 8; ++nt){
            const int cA = nbase + nt*8 + 2*(lane&3);
            float v0 = acc[mt][nt][2*h]   + obS[cA]   + et[cA];
            float v1 = acc[mt][nt][2*h+1] + obS[cA+1] + et[cA+1];
            *(float2*)(out + (size_t)(t0 + r)*256 + cA) = make_float2(v0, v1);
            s0 += v0*mwS[2*cA]   + v1*mwS[2*cA+2];
            s1 += v0*mwS[2*cA+1] + v1*mwS[2*cA+3];
        }
        s0 += __shfl_xor_sync(0xffffffffu, s0, 1); s1 += __shfl_xor_sync(0xffffffffu, s1, 1);
        s0 += __shfl_xor_sync(0xffffffffu, s0, 2); s1 += __shfl_xor_sync(0xffffffffu, s1, 2);
        if ((lane & 3) == 0){ atomicAdd(&lgp[r].x, s0); atomicAdd(&lgp[r].y, s1); }
    }
    __syncthreads();
    if (tid < 64){
        float2 p = lgp[tid];
        out[LOG_OFF + (size_t)(t0 + tid)*2 + 0] = p.x + MB[0];
        out[LOG_OFF + (size_t)(t0 + tid)*2 + 1] = p.y + MB[1];
    }
}

// ===========================================================================
extern "C" void kernel_launch(void* const* d_in, const int* in_sizes, int n_in,
                              void* d_out, int out_size)
{
    (void)in_sizes; (void)n_in; (void)out_size;
    const float* pos = (const float*)d_in[0];
    const float* ts  = (const float*)d_in[1];
    const float* W1  = (const float*)d_in[2];
    const float* EB1 = (const float*)d_in[3];
    const float* G1  = (const float*)d_in[4];
    const float* LB1 = (const float*)d_in[5];
    const float* W2  = (const float*)d_in[6];
    const float* EB2 = (const float*)d_in[7];
    const float* G2  = (const float*)d_in[8];
    const float* LB2 = (const float*)d_in[9];
    const float* EMB = (const float*)d_in[10];
    const float* OW  = (const float*)d_in[11];
    const float* OB  = (const float*)d_in[12];
    const float* MW  = (const float*)d_in[13];
    const float* MB  = (const float*)d_in[14];
    float* out = (float*)d_out;

    cudaFuncSetAttribute(mlp3_kernel, cudaFuncAttributeMaxDynamicSharedMemorySize, SMEM_SZ);

    dim3 g1(T_/256, B_);
    feat_kernel<<<g1, 256>>>(pos, ts, out + FLAG_OFF);
    prep_kernel<<<128, 256>>>(W2, OW, EMB);
    mlp3_kernel<<<BT_/64, NT, SMEM_SZ>>>(W1, EB1, G1, LB1, EB2, G2, LB2,
                                         OB, MW, MB, out);
}

// round 13
// speedup vs baseline: 1.4106x; 1.0700x over previous
#include <cuda_runtime.h>
#include <cuda_fp16.h>
#include <math.h>
#include <stdint.h>

// ---------------------------------------------------------------------------
// VelocityHead: B=64, T=4096, D=256, DE=16, NB=8, alpha=0.3, thresh=0.1
// Outputs (flat fp32): vel [B,T,256], move_flag [B,T], mov_logits [B,T,2]
// mma.sync f16, 2-product split (A single f16, W = f16 hi+lo).
// 64 tokens/CTA, 256 thr, 2 CTAs/SM, cp.async double-buffered W chunks.
// ---------------------------------------------------------------------------

#define B_    64
#define T_    4096
#define BT_   (B_*T_)
#define FLAG_OFF  (BT_*256)
#define LOG_OFF   (FLAG_OFF + BT_)
#define PI_F 3.14159265358979323846f

typedef unsigned long long ull;

// scratch (allocation-free: device globals)
__device__ float g_feats[BT_*6];
__device__ int   g_bins[BT_];
// weights f16 hi/lo, [K][N] row-major (k rows of 256)
__device__ __half g_w2h[256*256];
__device__ __half g_w2l[256*256];
__device__ __half g_owh[256*256];
__device__ __half g_owl[256*256];
__device__ float g_embtab[8*256];     // emb[bin] @ OW[256:272,:]

// ------------------------- packed f32x2 helpers ----------------------------
__device__ __forceinline__ ull pk2(float lo, float hi){
    ull r; asm("mov.b64 %0, {%1,%2};" : "=l"(r) : "f"(lo), "f"(hi)); return r;
}
__device__ __forceinline__ void upk2(ull v, float &lo, float &hi){
    asm("mov.b64 {%0,%1}, %2;" : "=f"(lo), "=f"(hi) : "l"(v));
}
__device__ __forceinline__ void fma2(ull &d, ull a, ull b){
    asm("fma.rn.f32x2 %0, %1, %2, %0;" : "+l"(d) : "l"(a), "l"(b));
}

// ------------------------- mma/ldmatrix/cp.async helpers -------------------
__device__ __forceinline__ uint32_t smem_u32(const void* p){
    uint32_t a;
    asm("{ .reg .u64 t; cvta.to.shared.u64 t, %1; cvt.u32.u64 %0, t; }" : "=r"(a) : "l"(p));
    return a;
}
__device__ __forceinline__ void ldm4(uint32_t* r, uint32_t addr){
    asm volatile("ldmatrix.sync.aligned.m8n8.x4.shared.b16 {%0,%1,%2,%3}, [%4];"
        : "=r"(r[0]), "=r"(r[1]), "=r"(r[2]), "=r"(r[3]) : "r"(addr));
}
__device__ __forceinline__ void ldm4t(uint32_t* r, uint32_t addr){
    asm volatile("ldmatrix.sync.aligned.m8n8.x4.trans.shared.b16 {%0,%1,%2,%3}, [%4];"
        : "=r"(r[0]), "=r"(r[1]), "=r"(r[2]), "=r"(r[3]) : "r"(addr));
}
__device__ __forceinline__ void mma_f16(float* c, const uint32_t* a, uint32_t b0, uint32_t b1){
    asm volatile("mma.sync.aligned.m16n8k16.row.col.f32.f16.f16.f32 "
        "{%0,%1,%2,%3}, {%4,%5,%6,%7}, {%8,%9}, {%0,%1,%2,%3};"
        : "+f"(c[0]), "+f"(c[1]), "+f"(c[2]), "+f"(c[3])
        : "r"(a[0]), "r"(a[1]), "r"(a[2]), "r"(a[3]), "r"(b0), "r"(b1));
}
__device__ __forceinline__ void cpasync16(uint32_t dst, const void* src){
    asm volatile("cp.async.cg.shared.global [%0], [%1], 16;" :: "r"(dst), "l"(src) : "memory");
}
#define CP_COMMIT() asm volatile("cp.async.commit_group;" ::: "memory")
#define CP_WAIT1()  asm volatile("cp.async.wait_group 1;" ::: "memory")
#define CP_WAIT0()  asm volatile("cp.async.wait_group 0;" ::: "memory")

__device__ __forceinline__ unsigned short f2h(float x){
    return __half_as_ushort(__float2half_rn(x));
}

// ===========================================================================
// prep: split weights to f16 hi/lo [K][N]; fold emb through OW tail.
// ===========================================================================
__global__ void prep_kernel(const float* __restrict__ W2, const float* __restrict__ OW,
                            const float* __restrict__ EMB){
    int i = blockIdx.x*blockDim.x + threadIdx.x;
    int stride = gridDim.x*blockDim.x;
    for (int x = i; x < 256*256; x += stride){
        float w = W2[x];
        __half h = __float2half_rn(w);
        g_w2h[x] = h;
        g_w2l[x] = __float2half_rn(w - __half2float(h));
        float w2 = OW[x];                // rows 0..255 of OW
        __half h2 = __float2half_rn(w2);
        g_owh[x] = h2;
        g_owl[x] = __float2half_rn(w2 - __half2float(h2));
    }
    for (int x = i; x < 8*256; x += stride){
        int j = x >> 8, n = x & 255;
        float s = 0.f;
        #pragma unroll
        for (int e = 0; e < 16; ++e)
            s += EMB[j*16 + e] * OW[(256 + e)*256 + n];
        g_embtab[x] = s;
    }
}

// ===========================================================================
// Kernel 1: features + windowed EMA (exact to fp32: 0.7^64 ~ 1.2e-10)
// ===========================================================================
__global__ __launch_bounds__(256)
void feat_kernel(const float* __restrict__ pos, const float* __restrict__ ts,
                 float* __restrict__ flag_out)
{
    __shared__ float sx[320], sd[320];
    const int b    = blockIdx.y;
    const int t0   = blockIdx.x * 256;
    const int tid  = threadIdx.x;
    const float* P  = pos + (size_t)b * T_ * 2;
    const float* Ts = ts  + (size_t)b * T_;

    float dPx_m, dPy_m, dt_m;
    auto compx = [&](int t, float &sp, float &dn, float &dx, float &dy, float &dtv){
        float dxx, dyy, dt;
        if (t == 0) { dxx = 0.f; dyy = 0.f; dt = 1.f; }
        else {
            dxx = P[2*t]   - P[2*t-2];
            dyy = P[2*t+1] - P[2*t-1];
            float dtr = Ts[t] - Ts[t-1];
            dtr = (dtr > 0.01f) ? dtr : 1.0f;
            dt  = fminf(fmaxf(dtr, 0.1f), 1000.f);
        }
        float dist = sqrtf(dxx*dxx + dyy*dyy) + 1e-8f;
        float dts  = fminf(fmaxf(dt, 0.1f), 1000.f) * 0.1f;
        sp = fminf(fmaxf(dist / (dts + 1e-6f), 0.f), 10.f);
        float dir = atan2f(dyy + 1e-8f, dxx + 1e-8f);
        dn = fminf(fmaxf(dir * (1.0f/PI_F), -1.f), 1.f);
        dx = dxx; dy = dyy; dtv = dt;
    };

    { float sp, dn; compx(t0 + tid, sp, dn, dPx_m, dPy_m, dt_m); sx[64+tid]=sp; sd[64+tid]=dn; }
    if (tid < 64 && t0 > 0){ float sp,dn,a0,a1,a2; compx(t0-64+tid,sp,dn,a0,a1,a2); sx[tid]=sp; sd[tid]=dn; }
    __syncthreads();

    const int   t  = t0 + tid;
    const float cA = 0.3f, cC = 0.7f;
    float ys, yd;
    if (t == 0) { ys = sx[64]; yd = sd[64]; }
    else {
        const int Kw     = (t < 64) ? t : 64;
        const int lstart = (t - Kw + 1) - t0 + 64;
        float ss = 0.f, sdd = 0.f;
        for (int l = lstart; l <= tid + 64; ++l) { ss = cC*ss + sx[l]; sdd = cC*sdd + sd[l]; }
        ys = cA*ss; yd = cA*sdd;
        if (t < 64) {
            float p = 1.f;
            for (int i = 0; i < t; ++i) p *= cC;
            ys += p * sx[64]; yd += p * sd[64];
        }
    }

    const float flag = (ys > 0.1f) ? 1.f : 0.f;
    const size_t g = (size_t)b * T_ + t;
    float* f = g_feats + g*6;
    f[0] = dPx_m; f[1] = dPy_m; f[2] = dt_m; f[3] = ys; f[4] = yd; f[5] = flag;

    int bin = (int)((yd + 1.0f) * 4.0f);
    bin = min(max(bin, 0), 7);
    if (flag == 0.f) bin = 0;
    g_bins[g]   = bin;
    flag_out[g] = flag;
}

// ===========================================================================
// Kernel 2: fused MLP with mma.sync f16 2-product split + cp.async W pipe.
// 64 tokens/CTA, 256 thr (8 warps). Warp tile 32x64 (2 m16 x 8 n8).
// ===========================================================================
#define NT 256
#define ASTRIDE 528
#define AH_OFF 0                  // 64 x 528 = 33792
#define WB_OFF 33792              // two W buffers, each Wh+Wl
#define WHALF  16896              // 32 rows x 528
#define WBUFSZ (2*WHALF)          // 33792
#define CONST_OFF 101376
#define SMEM_SZ (CONST_OFF + 7168)   // 108544 -> 2 CTAs/SM

__device__ __forceinline__ void issue_chunk(uint32_t sb, int buf,
        const unsigned char* gWh, const unsigned char* gWl, int c, int tid){
    const uint32_t base = sb + WB_OFF + buf*WBUFSZ;
    #pragma unroll
    for (int j = 0; j < 4; ++j){
        int u = tid + j*256, row = u >> 5, seg = u & 31;
        uint32_t off = (uint32_t)row*ASTRIDE + seg*16;
        cpasync16(base + off,         gWh + (size_t)c*16384 + row*512 + seg*16);
        cpasync16(base + WHALF + off, gWl + (size_t)c*16384 + row*512 + seg*16);
    }
    CP_COMMIT();
}

__device__ __forceinline__ void gemm_tc(uint32_t sb,
                                        const unsigned char* gWh, const unsigned char* gWl,
                                        float acc[2][8][4], int tid)
{
    const int lane = tid & 31, warp = tid >> 5;
    const int nw = warp & 3, mw = warp >> 2;
    const int arow   = mw*32 + (lane & 15);
    const int acoladd= (lane >= 16) ? 8 : 0;
    const int brow   = (lane & 15);
    const int bcol   = nw*64 + ((lane >= 16) ? 8 : 0);

    issue_chunk(sb, 0, gWh, gWl, 0, tid);
    issue_chunk(sb, 1, gWh, gWl, 1, tid);

    #pragma unroll 1
    for (int c = 0; c < 8; ++c){
        if (c < 7) { CP_WAIT1(); } else { CP_WAIT0(); }
        __syncthreads();   // chunk c visible to all; also orders A-panel stores (c==0)
        const uint32_t whb = sb + WB_OFF + (c & 1)*WBUFSZ;
        const uint32_t wlb = whb + WHALF;
        #pragma unroll
        for (int kk = 0; kk < 32; kk += 16){
            uint32_t ah[2][4];
            const uint32_t acol = (uint32_t)(c*32 + kk + acoladd)*2;
            ldm4(ah[0], sb + AH_OFF + arow*ASTRIDE + acol);
            ldm4(ah[1], sb + AH_OFF + (arow+16)*ASTRIDE + acol);
            #pragma unroll
            for (int nt = 0; nt < 4; ++nt){
                uint32_t bh[4], bl[4];
                const uint32_t boff = (uint32_t)(kk + brow)*ASTRIDE + (uint32_t)(bcol + nt*16)*2;
                ldm4t(bh, whb + boff);
                ldm4t(bl, wlb + boff);
                // term-major: same accumulator revisited only every 4 mma
                mma_f16(acc[0][2*nt],   ah[0], bh[0], bh[1]);
                mma_f16(acc[1][2*nt],   ah[1], bh[0], bh[1]);
                mma_f16(acc[0][2*nt+1], ah[0], bh[2], bh[3]);
                mma_f16(acc[1][2*nt+1], ah[1], bh[2], bh[3]);
                mma_f16(acc[0][2*nt],   ah[0], bl[0], bl[1]);
                mma_f16(acc[1][2*nt],   ah[1], bl[0], bl[1]);
                mma_f16(acc[0][2*nt+1], ah[0], bl[2], bl[3]);
                mma_f16(acc[1][2*nt+1], ah[1], bl[2], bl[3]);
            }
        }
        __syncthreads();   // all warps done with buf[c&1] before it is refilled
        if (c < 6) issue_chunk(sb, c & 1, gWh, gWl, c + 2, tid);
    }
}

__global__ __launch_bounds__(NT, 2)
void mlp3_kernel(const float* __restrict__ W1,  const float* __restrict__ EB1,
                 const float* __restrict__ G1,  const float* __restrict__ LB1,
                 const float* __restrict__ EB2, const float* __restrict__ G2,
                 const float* __restrict__ LB2, const float* __restrict__ OB,
                 const float* __restrict__ MW,  const float* __restrict__ MB,
                 float* __restrict__ out)
{
    extern __shared__ unsigned char smemc[];
    const uint32_t sb = smem_u32(smemc);
    const int tid = threadIdx.x;
    const int warp = tid >> 5, lane = tid & 31;
    const int t0 = blockIdx.x * 64;

    float*  eb2S = (float*)(smemc + CONST_OFF);
    float*  g2S  = eb2S + 256;
    float*  lb2S = eb2S + 512;
    float*  obS  = eb2S + 768;
    float*  mwS  = eb2S + 1024;          // 512 floats
    float2* lnp  = (float2*)(eb2S + 1536);   // 64 float2
    float2* lgp  = lnp + 64;                 // 64 float2

    float*  featS = (float*)(smemc + WB_OFF);        // 64x8 fp32 (buf0 area)
    float*  w1S   = featS + 512;                      // 6x256 fp32

    // stage consts + feats + W1
    eb2S[tid] = EB2[tid]; g2S[tid] = G2[tid]; lb2S[tid] = LB2[tid]; obS[tid] = OB[tid];
    mwS[tid] = MW[tid]; mwS[tid+256] = MW[tid+256];
    for (int i = tid; i < 64*6; i += NT) featS[(i/6)*8 + (i%6)] = g_feats[(size_t)t0*6 + i];
    for (int i = tid; i < 1536;  i += NT) w1S[i] = W1[i];
    if (tid < 64){ lnp[tid] = make_float2(0.f,0.f); lgp[tid] = make_float2(0.f,0.f); }
    __syncthreads();

    // ============ GEMM1 (K=6, fp32 FFMA2) + LN1 + ReLU -> A f16 panel ======
    {
        const int r0 = warp*8, c0 = lane*4;
        ull acc1[8][4];
        {
            float4 b0 = *(const float4*)(EB1 + c0);
            float4 b1 = *(const float4*)(EB1 + 128 + c0);
            ull p0 = pk2(b0.x,b0.y), p1 = pk2(b0.z,b0.w);
            ull p2 = pk2(b1.x,b1.y), p3 = pk2(b1.z,b1.w);
            #pragma unroll
            for (int i = 0; i < 8; ++i){ acc1[i][0]=p0; acc1[i][1]=p1; acc1[i][2]=p2; acc1[i][3]=p3; }
        }
        #pragma unroll
        for (int k = 0; k < 6; ++k){
            float4 w0 = *(const float4*)(w1S + k*256 + c0);
            float4 w1v= *(const float4*)(w1S + k*256 + 128 + c0);
            ull wp0 = pk2(w0.x,w0.y), wp1 = pk2(w0.z,w0.w);
            ull wp2 = pk2(w1v.x,w1v.y), wp3 = pk2(w1v.z,w1v.w);
            #pragma unroll
            for (int i = 0; i < 8; ++i){
                float f = featS[(r0+i)*8 + k];
                ull fp = pk2(f, f);
                fma2(acc1[i][0], fp, wp0); fma2(acc1[i][1], fp, wp1);
                fma2(acc1[i][2], fp, wp2); fma2(acc1[i][3], fp, wp3);
            }
        }
        float4 gA = *(const float4*)(G1 + c0);
        float4 gB = *(const float4*)(G1 + 128 + c0);
        float4 bA = *(const float4*)(LB1 + c0);
        float4 bB = *(const float4*)(LB1 + 128 + c0);
        float gg[8] = {gA.x,gA.y,gA.z,gA.w,gB.x,gB.y,gB.z,gB.w};
        float bb[8] = {bA.x,bA.y,bA.z,bA.w,bB.x,bB.y,bB.z,bB.w};
        #pragma unroll
        for (int i = 0; i < 8; ++i){
            float v[8];
            upk2(acc1[i][0], v[0], v[1]); upk2(acc1[i][1], v[2], v[3]);
            upk2(acc1[i][2], v[4], v[5]); upk2(acc1[i][3], v[6], v[7]);
            float s = 0.f, q = 0.f;
            #pragma unroll
            for (int j = 0; j < 8; ++j){ s += v[j]; q += v[j]*v[j]; }
            #pragma unroll
            for (int off = 16; off; off >>= 1){
                s += __shfl_xor_sync(0xffffffffu, s, off);
                q += __shfl_xor_sync(0xffffffffu, q, off);
            }
            float mean = s * (1.f/256.f);
            float var  = fmaf(-mean, mean, q * (1.f/256.f));
            float rstd = rsqrtf(var + 1e-5f);
            const int row = r0 + i;
            #pragma unroll
            for (int gph = 0; gph < 2; ++gph){
                const int cc = gph*128 + c0;
                float o0 = fmaxf((v[gph*4+0]-mean)*rstd*gg[gph*4+0] + bb[gph*4+0], 0.f);
                float o1 = fmaxf((v[gph*4+1]-mean)*rstd*gg[gph*4+1] + bb[gph*4+1], 0.f);
                float o2 = fmaxf((v[gph*4+2]-mean)*rstd*gg[gph*4+2] + bb[gph*4+2], 0.f);
                float o3 = fmaxf((v[gph*4+3]-mean)*rstd*gg[gph*4+3] + bb[gph*4+3], 0.f);
                *(uint2*)(smemc + AH_OFF + row*ASTRIDE + cc*2) =
                    make_uint2((uint32_t)f2h(o0) | ((uint32_t)f2h(o1)<<16),
                               (uint32_t)f2h(o2) | ((uint32_t)f2h(o3)<<16));
            }
        }
    }
    __syncthreads();   // featS fully consumed before cp.async overwrites buf0

    const int nw = warp & 3, mw = warp >> 2;
    const int mbase = mw*32, nbase = nw*64;

    float acc[2][8][4];
    #pragma unroll
    for (int a1 = 0; a1 < 2; ++a1)
        #pragma unroll
        for (int a2 = 0; a2 < 8; ++a2)
            #pragma unroll
            for (int a3 = 0; a3 < 4; ++a3) acc[a1][a2][a3] = 0.f;

    // ================= GEMM2: h @ W2 =======================================
    gemm_tc(sb, (const unsigned char*)g_w2h, (const unsigned char*)g_w2l, acc, tid);

    // ================= LN2 (bias + stats + normalize -> A f16) =============
    #pragma unroll
    for (int mt = 0; mt < 2; ++mt)
    #pragma unroll
    for (int h = 0; h < 2; ++h){
        const int r = mbase + mt*16 + h*8 + (lane>>2);
        float s = 0.f, q = 0.f;
        #pragma unroll
        for (int nt = 0; nt < 8; ++nt){
            const int cA = nbase + nt*8 + 2*(lane&3);
            float x0 = acc[mt][nt][2*h]   + eb2S[cA];
            float x1 = acc[mt][nt][2*h+1] + eb2S[cA+1];
            s += x0 + x1; q += x0*x0 + x1*x1;
        }
        s += __shfl_xor_sync(0xffffffffu, s, 1); q += __shfl_xor_sync(0xffffffffu, q, 1);
        s += __shfl_xor_sync(0xffffffffu, s, 2); q += __shfl_xor_sync(0xffffffffu, q, 2);
        if ((lane & 3) == 0){ atomicAdd(&lnp[r].x, s); atomicAdd(&lnp[r].y, q); }
    }
    __syncthreads();
    if (tid < 64){
        float2 p = lnp[tid];
        float mean = p.x * (1.f/256.f);
        float var  = fmaf(-mean, mean, p.y * (1.f/256.f));
        lnp[tid] = make_float2(mean, rsqrtf(var + 1e-5f));
    }
    __syncthreads();
    #pragma unroll
    for (int mt = 0; mt < 2; ++mt)
    #pragma unroll
    for (int h = 0; h < 2; ++h){
        const int r = mbase + mt*16 + h*8 + (lane>>2);
        const float2 st = lnp[r];
        #pragma unroll
        for (int nt = 0; nt < 8; ++nt){
            const int cA = nbase + nt*8 + 2*(lane&3);
            float x0 = (acc[mt][nt][2*h]   + eb2S[cA]   - st.x)*st.y*g2S[cA]   + lb2S[cA];
            float x1 = (acc[mt][nt][2*h+1] + eb2S[cA+1] - st.x)*st.y*g2S[cA+1] + lb2S[cA+1];
            *(uint32_t*)(smemc + AH_OFF + r*ASTRIDE + cA*2) =
                (uint32_t)f2h(x0) | ((uint32_t)f2h(x1)<<16);
        }
    }

    #pragma unroll
    for (int a1 = 0; a1 < 2; ++a1)
        #pragma unroll
        for (int a2 = 0; a2 < 8; ++a2)
            #pragma unroll
            for (int a3 = 0; a3 < 4; ++a3) acc[a1][a2][a3] = 0.f;

    // ================= GEMM3: base @ OW[:256] ==============================
    // gemm_tc's first in-loop barrier orders the LN2 A-panel stores.
    gemm_tc(sb, (const unsigned char*)g_owh, (const unsigned char*)g_owl, acc, tid);

    // ================= epilogue: vel + mov_logits ==========================
    #pragma unroll
    for (int mt = 0; mt < 2; ++mt)
    #pragma unroll
    for (int h = 0; h < 2; ++h){
        const int r = mbase + mt*16 + h*8 + (lane>>2);
        const int bin = g_bins[t0 + r];
        const float* et = g_embtab + bin*256;
        float s0 = 0.f, s1 = 0.f;
        #pragma unroll
        for (int nt = 0; nt < 8; ++nt){
            const int cA = nbase + nt*8 + 2*(lane&3);
            float v0 = acc[mt][nt][2*h]   + obS[cA]   + et[cA];
            float v1 = acc[mt][nt][2*h+1] + obS[cA+1] + et[cA+1];
            *(float2*)(out + (size_t)(t0 + r)*256 + cA) = make_float2(v0, v1);
            s0 += v0*mwS[2*cA]   + v1*mwS[2*cA+2];
            s1 += v0*mwS[2*cA+1] + v1*mwS[2*cA+3];
        }
        s0 += __shfl_xor_sync(0xffffffffu, s0, 1); s1 += __shfl_xor_sync(0xffffffffu, s1, 1);
        s0 += __shfl_xor_sync(0xffffffffu, s0, 2); s1 += __shfl_xor_sync(0xffffffffu, s1, 2);
        if ((lane & 3) == 0){ atomicAdd(&lgp[r].x, s0); atomicAdd(&lgp[r].y, s1); }
    }
    __syncthreads();
    if (tid < 64){
        float2 p = lgp[tid];
        out[LOG_OFF + (size_t)(t0 + tid)*2 + 0] = p.x + MB[0];
        out[LOG_OFF + (size_t)(t0 + tid)*2 + 1] = p.y + MB[1];
    }
}

// ===========================================================================
extern "C" void kernel_launch(void* const* d_in, const int* in_sizes, int n_in,
                              void* d_out, int out_size)
{
    (void)in_sizes; (void)n_in; (void)out_size;
    const float* pos = (const float*)d_in[0];
    const float* ts  = (const float*)d_in[1];
    const float* W1  = (const float*)d_in[2];
    const float* EB1 = (const float*)d_in[3];
    const float* G1  = (const float*)d_in[4];
    const float* LB1 = (const float*)d_in[5];
    const float* W2  = (const float*)d_in[6];
    const float* EB2 = (const float*)d_in[7];
    const float* G2  = (const float*)d_in[8];
    const float* LB2 = (const float*)d_in[9];
    const float* EMB = (const float*)d_in[10];
    const float* OW  = (const float*)d_in[11];
    const float* OB  = (const float*)d_in[12];
    const float* MW  = (const float*)d_in[13];
    const float* MB  = (const float*)d_in[14];
    float* out = (float*)d_out;

    cudaFuncSetAttribute(mlp3_kernel, cudaFuncAttributeMaxDynamicSharedMemorySize, SMEM_SZ);

    dim3 g1(T_/256, B_);
    feat_kernel<<<g1, 256>>>(pos, ts, out + FLAG_OFF);
    prep_kernel<<<128, 256>>>(W2, OW, EMB);
    mlp3_kernel<<<BT_/64, NT, SMEM_SZ>>>(W1, EB1, G1, LB1, EB2, G2, LB2,
                                         OB, MW, MB, out);
}

// round 17
// speedup vs baseline: 1.4527x; 1.0298x over previous
#include <cuda_runtime.h>
#include <cuda_fp16.h>
#include <math.h>
#include <stdint.h>

// ---------------------------------------------------------------------------
// VelocityHead: B=64, T=4096, D=256, DE=16, NB=8, alpha=0.3, thresh=0.1
// Outputs (flat fp32): vel [B,T,256], move_flag [B,T], mov_logits [B,T,2]
// mma.sync f16, 2-product split (A single f16, W = f16 hi+lo).
// 64 tokens/CTA, 256 thr, 2 CTAs/SM, cp.async double-buffered W chunks,
// first chunks pre-issued behind GEMM1 / LN2. feat+prep fused in one launch.
// ---------------------------------------------------------------------------

#define B_    64
#define T_    4096
#define BT_   (B_*T_)
#define FLAG_OFF  (BT_*256)
#define LOG_OFF   (FLAG_OFF + BT_)
#define PI_F 3.14159265358979323846f

typedef unsigned long long ull;

// scratch (allocation-free: device globals)
__device__ float g_feats[BT_*6];
__device__ int   g_bins[BT_];
// weights f16 hi/lo, [K][N] row-major (k rows of 256)
__device__ __half g_w2h[256*256];
__device__ __half g_w2l[256*256];
__device__ __half g_owh[256*256];
__device__ __half g_owl[256*256];
__device__ float g_embtab[8*256];     // emb[bin] @ OW[256:272,:]

// ------------------------- packed f32x2 helpers ----------------------------
__device__ __forceinline__ ull pk2(float lo, float hi){
    ull r; asm("mov.b64 %0, {%1,%2};" : "=l"(r) : "f"(lo), "f"(hi)); return r;
}
__device__ __forceinline__ void upk2(ull v, float &lo, float &hi){
    asm("mov.b64 {%0,%1}, %2;" : "=f"(lo), "=f"(hi) : "l"(v));
}
__device__ __forceinline__ void fma2(ull &d, ull a, ull b){
    asm("fma.rn.f32x2 %0, %1, %2, %0;" : "+l"(d) : "l"(a), "l"(b));
}

// ------------------------- mma/ldmatrix/cp.async helpers -------------------
__device__ __forceinline__ uint32_t smem_u32(const void* p){
    uint32_t a;
    asm("{ .reg .u64 t; cvta.to.shared.u64 t, %1; cvt.u32.u64 %0, t; }" : "=r"(a) : "l"(p));
    return a;
}
__device__ __forceinline__ void ldm4(uint32_t* r, uint32_t addr){
    asm volatile("ldmatrix.sync.aligned.m8n8.x4.shared.b16 {%0,%1,%2,%3}, [%4];"
        : "=r"(r[0]), "=r"(r[1]), "=r"(r[2]), "=r"(r[3]) : "r"(addr));
}
__device__ __forceinline__ void ldm4t(uint32_t* r, uint32_t addr){
    asm volatile("ldmatrix.sync.aligned.m8n8.x4.trans.shared.b16 {%0,%1,%2,%3}, [%4];"
        : "=r"(r[0]), "=r"(r[1]), "=r"(r[2]), "=r"(r[3]) : "r"(addr));
}
__device__ __forceinline__ void mma_f16(float* c, const uint32_t* a, uint32_t b0, uint32_t b1){
    asm volatile("mma.sync.aligned.m16n8k16.row.col.f32.f16.f16.f32 "
        "{%0,%1,%2,%3}, {%4,%5,%6,%7}, {%8,%9}, {%0,%1,%2,%3};"
        : "+f"(c[0]), "+f"(c[1]), "+f"(c[2]), "+f"(c[3])
        : "r"(a[0]), "r"(a[1]), "r"(a[2]), "r"(a[3]), "r"(b0), "r"(b1));
}
__device__ __forceinline__ void cpasync16(uint32_t dst, const void* src){
    asm volatile("cp.async.cg.shared.global [%0], [%1], 16;" :: "r"(dst), "l"(src) : "memory");
}
#define CP_COMMIT() asm volatile("cp.async.commit_group;" ::: "memory")
#define CP_WAIT1()  asm volatile("cp.async.wait_group 1;" ::: "memory")
#define CP_WAIT0()  asm volatile("cp.async.wait_group 0;" ::: "memory")

__device__ __forceinline__ unsigned short f2h(float x){
    return __half_as_ushort(__float2half_rn(x));
}

// ===========================================================================
// Kernel 1 (fused): blocks [0,1024) = features + windowed EMA;
//                   blocks [1024,1088) = weight split prep + emb fold.
// ===========================================================================
__global__ __launch_bounds__(256)
void featprep_kernel(const float* __restrict__ pos, const float* __restrict__ ts,
                     float* __restrict__ flag_out,
                     const float* __restrict__ W2, const float* __restrict__ OW,
                     const float* __restrict__ EMB)
{
    const int tid = threadIdx.x;
    if (blockIdx.x >= 1024){
        // -------- prep part --------
        int i = (blockIdx.x - 1024)*256 + tid;
        const int stride = 64*256;
        for (int x = i; x < 256*256; x += stride){
            float w = W2[x];
            __half h = __float2half_rn(w);
            g_w2h[x] = h;
            g_w2l[x] = __float2half_rn(w - __half2float(h));
            float w2 = OW[x];                // rows 0..255 of OW
            __half h2 = __float2half_rn(w2);
            g_owh[x] = h2;
            g_owl[x] = __float2half_rn(w2 - __half2float(h2));
        }
        for (int x = i; x < 8*256; x += stride){
            int j = x >> 8, n = x & 255;
            float s = 0.f;
            #pragma unroll
            for (int e = 0; e < 16; ++e)
                s += EMB[j*16 + e] * OW[(256 + e)*256 + n];
            g_embtab[x] = s;
        }
        return;
    }

    // -------- feat part --------
    __shared__ float sx[320], sd[320];
    const int b  = blockIdx.x >> 4;
    const int t0 = (blockIdx.x & 15) * 256;
    const float* P  = pos + (size_t)b * T_ * 2;
    const float* Ts = ts  + (size_t)b * T_;

    float dPx_m, dPy_m, dt_m;
    auto compx = [&](int t, float &sp, float &dn, float &dx, float &dy, float &dtv){
        float dxx, dyy, dt;
        if (t == 0) { dxx = 0.f; dyy = 0.f; dt = 1.f; }
        else {
            dxx = P[2*t]   - P[2*t-2];
            dyy = P[2*t+1] - P[2*t-1];
            float dtr = Ts[t] - Ts[t-1];
            dtr = (dtr > 0.01f) ? dtr : 1.0f;
            dt  = fminf(fmaxf(dtr, 0.1f), 1000.f);
        }
        float dist = sqrtf(dxx*dxx + dyy*dyy) + 1e-8f;
        float dts  = fminf(fmaxf(dt, 0.1f), 1000.f) * 0.1f;
        sp = fminf(fmaxf(dist / (dts + 1e-6f), 0.f), 10.f);
        float dir = atan2f(dyy + 1e-8f, dxx + 1e-8f);
        dn = fminf(fmaxf(dir * (1.0f/PI_F), -1.f), 1.f);
        dx = dxx; dy = dyy; dtv = dt;
    };

    { float sp, dn; compx(t0 + tid, sp, dn, dPx_m, dPy_m, dt_m); sx[64+tid]=sp; sd[64+tid]=dn; }
    if (tid < 64 && t0 > 0){ float sp,dn,a0,a1,a2; compx(t0-64+tid,sp,dn,a0,a1,a2); sx[tid]=sp; sd[tid]=dn; }
    __syncthreads();

    const int   t  = t0 + tid;
    const float cA = 0.3f, cC = 0.7f;
    float ys, yd;
    if (t == 0) { ys = sx[64]; yd = sd[64]; }
    else {
        const int Kw     = (t < 64) ? t : 64;
        const int lstart = (t - Kw + 1) - t0 + 64;
        float ss = 0.f, sdd = 0.f;
        for (int l = lstart; l <= tid + 64; ++l) { ss = cC*ss + sx[l]; sdd = cC*sdd + sd[l]; }
        ys = cA*ss; yd = cA*sdd;
        if (t < 64) {
            float p = 1.f;
            for (int i = 0; i < t; ++i) p *= cC;
            ys += p * sx[64]; yd += p * sd[64];
        }
    }

    const float flag = (ys > 0.1f) ? 1.f : 0.f;
    const size_t g = (size_t)b * T_ + t;
    float* f = g_feats + g*6;
    f[0] = dPx_m; f[1] = dPy_m; f[2] = dt_m; f[3] = ys; f[4] = yd; f[5] = flag;

    int bin = (int)((yd + 1.0f) * 4.0f);
    bin = min(max(bin, 0), 7);
    if (flag == 0.f) bin = 0;
    g_bins[g]   = bin;
    flag_out[g] = flag;
}

// ===========================================================================
// Kernel 2: fused MLP with mma.sync f16 2-product split + cp.async W pipe.
// 64 tokens/CTA, 256 thr (8 warps). Warp tile 32x64 (2 m16 x 8 n8).
// ===========================================================================
#define NT 256
#define ASTRIDE 528
#define AH_OFF 0                  // 64 x 528 = 33792
#define WB_OFF 33792              // two W buffers, each Wh+Wl
#define WHALF  16896              // 32 rows x 528
#define WBUFSZ (2*WHALF)          // 33792
#define CONST_OFF 101376
#define SMEM_SZ (CONST_OFF + 9216)   // consts 7168B + featS 2048B = 110592 -> 2 CTAs/SM

__device__ __forceinline__ void issue_chunk(uint32_t sb, int buf,
        const unsigned char* gWh, const unsigned char* gWl, int c, int tid){
    const uint32_t base = sb + WB_OFF + buf*WBUFSZ;
    #pragma unroll
    for (int j = 0; j < 4; ++j){
        int u = tid + j*256, row = u >> 5, seg = u & 31;
        uint32_t off = (uint32_t)row*ASTRIDE + seg*16;
        cpasync16(base + off,         gWh + (size_t)c*16384 + row*512 + seg*16);
        cpasync16(base + WHALF + off, gWl + (size_t)c*16384 + row*512 + seg*16);
    }
    CP_COMMIT();
}

// Chunks 0 and 1 must already be in flight (issued by the caller).
__device__ __forceinline__ void gemm_tc(uint32_t sb,
                                        const unsigned char* gWh, const unsigned char* gWl,
                                        float acc[2][8][4], int tid)
{
    const int lane = tid & 31, warp = tid >> 5;
    const int nw = warp & 3, mw = warp >> 2;
    const int arow   = mw*32 + (lane & 15);
    const int acoladd= (lane >= 16) ? 8 : 0;
    const int brow   = (lane & 15);
    const int bcol   = nw*64 + ((lane >= 16) ? 8 : 0);

    #pragma unroll 1
    for (int c = 0; c < 8; ++c){
        if (c < 7) { CP_WAIT1(); } else { CP_WAIT0(); }
        __syncthreads();   // chunk c visible to all; also orders A-panel stores (c==0)
        const uint32_t whb = sb + WB_OFF + (c & 1)*WBUFSZ;
        const uint32_t wlb = whb + WHALF;
        #pragma unroll
        for (int kk = 0; kk < 32; kk += 16){
            uint32_t ah[2][4];
            const uint32_t acol = (uint32_t)(c*32 + kk + acoladd)*2;
            ldm4(ah[0], sb + AH_OFF + arow*ASTRIDE + acol);
            ldm4(ah[1], sb + AH_OFF + (arow+16)*ASTRIDE + acol);
            #pragma unroll
            for (int nt = 0; nt < 4; ++nt){
                uint32_t bh[4], bl[4];
                const uint32_t boff = (uint32_t)(kk + brow)*ASTRIDE + (uint32_t)(bcol + nt*16)*2;
                ldm4t(bh, whb + boff);
                ldm4t(bl, wlb + boff);
                // term-major: same accumulator revisited only every 4 mma
                mma_f16(acc[0][2*nt],   ah[0], bh[0], bh[1]);
                mma_f16(acc[1][2*nt],   ah[1], bh[0], bh[1]);
                mma_f16(acc[0][2*nt+1], ah[0], bh[2], bh[3]);
                mma_f16(acc[1][2*nt+1], ah[1], bh[2], bh[3]);
                mma_f16(acc[0][2*nt],   ah[0], bl[0], bl[1]);
                mma_f16(acc[1][2*nt],   ah[1], bl[0], bl[1]);
                mma_f16(acc[0][2*nt+1], ah[0], bl[2], bl[3]);
                mma_f16(acc[1][2*nt+1], ah[1], bl[2], bl[3]);
            }
        }
        __syncthreads();   // all warps done with buf[c&1] before it is refilled
        if (c < 6) issue_chunk(sb, c & 1, gWh, gWl, c + 2, tid);
    }
}

__global__ __launch_bounds__(NT, 2)
void mlp3_kernel(const float* __restrict__ W1,  const float* __restrict__ EB1,
                 const float* __restrict__ G1,  const float* __restrict__ LB1,
                 const float* __restrict__ EB2, const float* __restrict__ G2,
                 const float* __restrict__ LB2, const float* __restrict__ OB,
                 const float* __restrict__ MW,  const float* __restrict__ MB,
                 float* __restrict__ out)
{
    extern __shared__ unsigned char smemc[];
    const uint32_t sb = smem_u32(smemc);
    const int tid = threadIdx.x;
    const int warp = tid >> 5, lane = tid & 31;
    const int t0 = blockIdx.x * 64;

    float*  eb2S = (float*)(smemc + CONST_OFF);
    float*  g2S  = eb2S + 256;
    float*  lb2S = eb2S + 512;
    float*  obS  = eb2S + 768;
    float*  mwS  = eb2S + 1024;          // 512 floats
    float2* lnp  = (float2*)(eb2S + 1536);   // 64 float2
    float2* lgp  = lnp + 64;                 // 64 float2 (ends at 7168B)
    float*  featS= eb2S + 1792;              // 512 floats (64x8), ends at 9216B

    // kick off W2 chunks 0,1 immediately — latency hidden behind GEMM1/LN1
    issue_chunk(sb, 0, (const unsigned char*)g_w2h, (const unsigned char*)g_w2l, 0, tid);
    issue_chunk(sb, 1, (const unsigned char*)g_w2h, (const unsigned char*)g_w2l, 1, tid);

    // stage consts + feats
    eb2S[tid] = EB2[tid]; g2S[tid] = G2[tid]; lb2S[tid] = LB2[tid]; obS[tid] = OB[tid];
    mwS[tid] = MW[tid]; mwS[tid+256] = MW[tid+256];
    for (int i = tid; i < 64*6; i += NT) featS[(i/6)*8 + (i%6)] = g_feats[(size_t)t0*6 + i];
    if (tid < 64){ lnp[tid] = make_float2(0.f,0.f); lgp[tid] = make_float2(0.f,0.f); }
    __syncthreads();

    // ============ GEMM1 (K=6, fp32 FFMA2, W1 from global) + LN1 + ReLU =====
    {
        const int r0 = warp*8, c0 = lane*4;
        ull acc1[8][4];
        {
            float4 b0 = *(const float4*)(EB1 + c0);
            float4 b1 = *(const float4*)(EB1 + 128 + c0);
            ull p0 = pk2(b0.x,b0.y), p1 = pk2(b0.z,b0.w);
            ull p2 = pk2(b1.x,b1.y), p3 = pk2(b1.z,b1.w);
            #pragma unroll
            for (int i = 0; i < 8; ++i){ acc1[i][0]=p0; acc1[i][1]=p1; acc1[i][2]=p2; acc1[i][3]=p3; }
        }
        #pragma unroll
        for (int k = 0; k < 6; ++k){
            float4 w0 = *(const float4*)(W1 + k*256 + c0);
            float4 w1v= *(const float4*)(W1 + k*256 + 128 + c0);
            ull wp0 = pk2(w0.x,w0.y), wp1 = pk2(w0.z,w0.w);
            ull wp2 = pk2(w1v.x,w1v.y), wp3 = pk2(w1v.z,w1v.w);
            #pragma unroll
            for (int i = 0; i < 8; ++i){
                float f = featS[(r0+i)*8 + k];
                ull fp = pk2(f, f);
                fma2(acc1[i][0], fp, wp0); fma2(acc1[i][1], fp, wp1);
                fma2(acc1[i][2], fp, wp2); fma2(acc1[i][3], fp, wp3);
            }
        }
        float4 gA = *(const float4*)(G1 + c0);
        float4 gB = *(const float4*)(G1 + 128 + c0);
        float4 bA = *(const float4*)(LB1 + c0);
        float4 bB = *(const float4*)(LB1 + 128 + c0);
        float gg[8] = {gA.x,gA.y,gA.z,gA.w,gB.x,gB.y,gB.z,gB.w};
        float bb[8] = {bA.x,bA.y,bA.z,bA.w,bB.x,bB.y,bB.z,bB.w};
        #pragma unroll
        for (int i = 0; i < 8; ++i){
            float v[8];
            upk2(acc1[i][0], v[0], v[1]); upk2(acc1[i][1], v[2], v[3]);
            upk2(acc1[i][2], v[4], v[5]); upk2(acc1[i][3], v[6], v[7]);
            float s = 0.f, q = 0.f;
            #pragma unroll
            for (int j = 0; j < 8; ++j){ s += v[j]; q += v[j]*v[j]; }
            #pragma unroll
            for (int off = 16; off; off >>= 1){
                s += __shfl_xor_sync(0xffffffffu, s, off);
                q += __shfl_xor_sync(0xffffffffu, q, off);
            }
            float mean = s * (1.f/256.f);
            float var  = fmaf(-mean, mean, q * (1.f/256.f));
            float rstd = rsqrtf(var + 1e-5f);
            const int row = r0 + i;
            #pragma unroll
            for (int gph = 0; gph < 2; ++gph){
                const int cc = gph*128 + c0;
                float o0 = fmaxf((v[gph*4+0]-mean)*rstd*gg[gph*4+0] + bb[gph*4+0], 0.f);
                float o1 = fmaxf((v[gph*4+1]-mean)*rstd*gg[gph*4+1] + bb[gph*4+1], 0.f);
                float o2 = fmaxf((v[gph*4+2]-mean)*rstd*gg[gph*4+2] + bb[gph*4+2], 0.f);
                float o3 = fmaxf((v[gph*4+3]-mean)*rstd*gg[gph*4+3] + bb[gph*4+3], 0.f);
                *(uint2*)(smemc + AH_OFF + row*ASTRIDE + cc*2) =
                    make_uint2((uint32_t)f2h(o0) | ((uint32_t)f2h(o1)<<16),
                               (uint32_t)f2h(o2) | ((uint32_t)f2h(o3)<<16));
            }
        }
    }
    // gemm_tc's first in-loop barrier orders the A-panel stores.

    const int nw = warp & 3, mw = warp >> 2;
    const int mbase = mw*32, nbase = nw*64;

    float acc[2][8][4];
    #pragma unroll
    for (int a1 = 0; a1 < 2; ++a1)
        #pragma unroll
        for (int a2 = 0; a2 < 8; ++a2)
            #pragma unroll
            for (int a3 = 0; a3 < 4; ++a3) acc[a1][a2][a3] = 0.f;

    // ================= GEMM2: h @ W2 =======================================
    gemm_tc(sb, (const unsigned char*)g_w2h, (const unsigned char*)g_w2l, acc, tid);

    // kick off OW chunks 0,1 now — latency hidden behind LN2
    issue_chunk(sb, 0, (const unsigned char*)g_owh, (const unsigned char*)g_owl, 0, tid);
    issue_chunk(sb, 1, (const unsigned char*)g_owh, (const unsigned char*)g_owl, 1, tid);

    // ================= LN2 (bias + stats + normalize -> A f16) =============
    #pragma unroll
    for (int mt = 0; mt < 2; ++mt)
    #pragma unroll
    for (int h = 0; h < 2; ++h){
        const int r = mbase + mt*16 + h*8 + (lane>>2);
        float s = 0.f, q = 0.f;
        #pragma unroll
        for (int nt = 0; nt < 8; ++nt){
            const int cA = nbase + nt*8 + 2*(lane&3);
            float x0 = acc[mt][nt][2*h]   + eb2S[cA];
            float x1 = acc[mt][nt][2*h+1] + eb2S[cA+1];
            s += x0 + x1; q += x0*x0 + x1*x1;
        }
        s += __shfl_xor_sync(0xffffffffu, s, 1); q += __shfl_xor_sync(0xffffffffu, q, 1);
        s += __shfl_xor_sync(0xffffffffu, s, 2); q += __shfl_xor_sync(0xffffffffu, q, 2);
        if ((lane & 3) == 0){ atomicAdd(&lnp[r].x, s); atomicAdd(&lnp[r].y, q); }
    }
    __syncthreads();
    if (tid < 64){
        float2 p = lnp[tid];
        float mean = p.x * (1.f/256.f);
        float var  = fmaf(-mean, mean, p.y * (1.f/256.f));
        lnp[tid] = make_float2(mean, rsqrtf(var + 1e-5f));
    }
    __syncthreads();
    #pragma unroll
    for (int mt = 0; mt < 2; ++mt)
    #pragma unroll
    for (int h = 0; h < 2; ++h){
        const int r = mbase + mt*16 + h*8 + (lane>>2);
        const float2 st = lnp[r];
        #pragma unroll
        for (int nt = 0; nt < 8; ++nt){
            const int cA = nbase + nt*8 + 2*(lane&3);
            float x0 = (acc[mt][nt][2*h]   + eb2S[cA]   - st.x)*st.y*g2S[cA]   + lb2S[cA];
            float x1 = (acc[mt][nt][2*h+1] + eb2S[cA+1] - st.x)*st.y*g2S[cA+1] + lb2S[cA+1];
            *(uint32_t*)(smemc + AH_OFF + r*ASTRIDE + cA*2) =
                (uint32_t)f2h(x0) | ((uint32_t)f2h(x1)<<16);
        }
    }

    #pragma unroll
    for (int a1 = 0; a1 < 2; ++a1)
        #pragma unroll
        for (int a2 = 0; a2 < 8; ++a2)
            #pragma unroll
            for (int a3 = 0; a3 < 4; ++a3) acc[a1][a2][a3] = 0.f;

    // ================= GEMM3: base @ OW[:256] ==============================
    // gemm_tc's first in-loop barrier orders the LN2 A-panel stores.
    gemm_tc(sb, (const unsigned char*)g_owh, (const unsigned char*)g_owl, acc, tid);

    // ================= epilogue: vel + mov_logits ==========================
    #pragma unroll
    for (int mt = 0; mt < 2; ++mt)
    #pragma unroll
    for (int h = 0; h < 2; ++h){
        const int r = mbase + mt*16 + h*8 + (lane>>2);
        const int bin = g_bins[t0 + r];
        const float* et = g_embtab + bin*256;
        float s0 = 0.f, s1 = 0.f;
        #pragma unroll
        for (int nt = 0; nt < 8; ++nt){
            const int cA = nbase + nt*8 + 2*(lane&3);
            float v0 = acc[mt][nt][2*h]   + obS[cA]   + et[cA];
            float v1 = acc[mt][nt][2*h+1] + obS[cA+1] + et[cA+1];
            *(float2*)(out + (size_t)(t0 + r)*256 + cA) = make_float2(v0, v1);
            s0 += v0*mwS[2*cA]   + v1*mwS[2*cA+2];
            s1 += v0*mwS[2*cA+1] + v1*mwS[2*cA+3];
        }
        s0 += __shfl_xor_sync(0xffffffffu, s0, 1); s1 += __shfl_xor_sync(0xffffffffu, s1, 1);
        s0 += __shfl_xor_sync(0xffffffffu, s0, 2); s1 += __shfl_xor_sync(0xffffffffu, s1, 2);
        if ((lane & 3) == 0){ atomicAdd(&lgp[r].x, s0); atomicAdd(&lgp[r].y, s1); }
    }
    __syncthreads();
    if (tid < 64){
        float2 p = lgp[tid];
        out[LOG_OFF + (size_t)(t0 + tid)*2 + 0] = p.x + MB[0];
        out[LOG_OFF + (size_t)(t0 + tid)*2 + 1] = p.y + MB[1];
    }
}

// ===========================================================================
extern "C" void kernel_launch(void* const* d_in, const int* in_sizes, int n_in,
                              void* d_out, int out_size)
{
    (void)in_sizes; (void)n_in; (void)out_size;
    const float* pos = (const float*)d_in[0];
    const float* ts  = (const float*)d_in[1];
    const float* W1  = (const float*)d_in[2];
    const float* EB1 = (const float*)d_in[3];
    const float* G1  = (const float*)d_in[4];
    const float* LB1 = (const float*)d_in[5];
    const float* W2  = (const float*)d_in[6];
    const float* EB2 = (const float*)d_in[7];
    const float* G2  = (const float*)d_in[8];
    const float* LB2 = (const float*)d_in[9];
    const float* EMB = (const float*)d_in[10];
    const float* OW  = (const float*)d_in[11];
    const float* OB  = (const float*)d_in[12];
    const float* MW  = (const float*)d_in[13];
    const float* MB  = (const float*)d_in[14];
    float* out = (float*)d_out;

    cudaFuncSetAttribute(mlp3_kernel, cudaFuncAttributeMaxDynamicSharedMemorySize, SMEM_SZ);

    featprep_kernel<<<1024 + 64, 256>>>(pos, ts, out + FLAG_OFF, W2, OW, EMB);
    mlp3_kernel<<<BT_/64, NT, SMEM_SZ>>>(W1, EB1, G1, LB1, EB2, G2, LB2,
                                         OB, MW, MB, out);
}